// round 1
// baseline (speedup 1.0000x reference)
#include <cuda_runtime.h>
#include <math.h>

#define NN   50000
#define EE   800000
#define DIN_ 128
#define H_   64
#define GD   256   // HEADS*H

// ---------------- scratch (static device arrays; no allocation) ----------------
__device__ float g_h0[NN * H_];    // x @ W_gcn
__device__ float g_h [NN * H_];    // GCN output (relu)
__device__ float g_g [NN * GD];    // h @ W_gat
__device__ float g_g2[NN * GD];    // GAT output (relu)
__device__ float g_mn[NN * GD];    // SAGE mean aggregate
__device__ float g_s [NN * H_];    // SAGE output
__device__ float g_u [NN * H_];    // s @ W1_top
__device__ float g_v [NN * H_];    // s @ W1_bot
__device__ float g_as[NN * 4];     // attention src logits
__device__ float g_ad[NN * 4];     // attention dst logits
__device__ int   g_cnt[NN];        // in-degree (no self loop)
__device__ int   g_cur[NN];        // fill cursor
__device__ int   g_rs [NN + 1];    // CSR row starts (by dst)
__device__ int   g_csrc[EE];       // CSR: src node per slot

__device__ __forceinline__ float lrelu(float x) { return x > 0.f ? x : 0.2f * x; }

// ---------------- CSR build ----------------
__global__ void init_kernel(int* __restrict__ cnt, int* __restrict__ cur) {
    int i = blockIdx.x * blockDim.x + threadIdx.x;
    if (i < NN) { cnt[i] = 0; cur[i] = 0; }
}

__global__ void hist_kernel(const int* __restrict__ dst, int* __restrict__ cnt) {
    int e = blockIdx.x * blockDim.x + threadIdx.x;
    if (e < EE) atomicAdd(&cnt[dst[e]], 1);
}

__global__ void scan_kernel(const int* __restrict__ cnt, int* __restrict__ rs) {
    __shared__ int buf[1024];
    __shared__ int carry;
    int tid = threadIdx.x;
    if (tid == 0) carry = 0;
    __syncthreads();
    for (int base = 0; base < NN; base += 1024) {
        int i = base + tid;
        int vcur = (i < NN) ? cnt[i] : 0;
        buf[tid] = vcur;
        __syncthreads();
        #pragma unroll
        for (int off = 1; off < 1024; off <<= 1) {
            int t = (tid >= off) ? buf[tid - off] : 0;
            __syncthreads();
            buf[tid] += t;
            __syncthreads();
        }
        if (i < NN) rs[i] = carry + buf[tid] - vcur;   // exclusive scan
        __syncthreads();
        if (tid == 0) carry += buf[1023];
        __syncthreads();
    }
    if (tid == 0) rs[NN] = carry;
}

__global__ void fill_kernel(const int* __restrict__ src, const int* __restrict__ dst,
                            const int* __restrict__ rs, int* __restrict__ cur,
                            int* __restrict__ csrc) {
    int e = blockIdx.x * blockDim.x + threadIdx.x;
    if (e < EE) {
        int d = dst[e];
        int pos = atomicAdd(&cur[d], 1);
        csrc[rs[d] + pos] = src[e];
    }
}

// ---------------- generic tiled GEMM: C[n,M] = A[n,K] @ W[K,M] ----------------
// K % 32 == 0, M % 64 == 0. Optional accumulate into C, optional bias+relu.
template <bool ACCUM, bool BIASRELU>
__global__ void gemm64(const float* __restrict__ A, const float* __restrict__ W,
                       float* __restrict__ C, const float* __restrict__ bias,
                       int n, int K, int M) {
    __shared__ float As[32][64];
    __shared__ float Ws[32][68];
    int row0 = blockIdx.y * 64;
    int col0 = blockIdx.x * 64;
    int tx = threadIdx.x & 15, ty = threadIdx.x >> 4;
    float acc[4][4] = {};
    for (int k0 = 0; k0 < K; k0 += 32) {
        for (int t = threadIdx.x; t < 512; t += 256) {  // A tile: 64 rows x 32 k
            int r = t >> 3, kq = t & 7;
            int row = row0 + r;
            float4 val = make_float4(0.f, 0.f, 0.f, 0.f);
            if (row < n) val = *(const float4*)(A + (size_t)row * K + k0 + kq * 4);
            As[kq * 4 + 0][r] = val.x;
            As[kq * 4 + 1][r] = val.y;
            As[kq * 4 + 2][r] = val.z;
            As[kq * 4 + 3][r] = val.w;
        }
        for (int t = threadIdx.x; t < 512; t += 256) {  // W tile: 32 k x 64 cols
            int kk = t >> 4, cq = t & 15;
            float4 val = *(const float4*)(W + (size_t)(k0 + kk) * M + col0 + cq * 4);
            *(float4*)&Ws[kk][cq * 4] = val;
        }
        __syncthreads();
        #pragma unroll
        for (int kk = 0; kk < 32; kk++) {
            float a[4], b[4];
            #pragma unroll
            for (int i = 0; i < 4; i++) a[i] = As[kk][ty * 4 + i];
            #pragma unroll
            for (int j = 0; j < 4; j++) b[j] = Ws[kk][tx * 4 + j];
            #pragma unroll
            for (int i = 0; i < 4; i++)
                #pragma unroll
                for (int j = 0; j < 4; j++) acc[i][j] += a[i] * b[j];
        }
        __syncthreads();
    }
    #pragma unroll
    for (int i = 0; i < 4; i++) {
        int row = row0 + ty * 4 + i;
        if (row >= n) continue;
        #pragma unroll
        for (int j = 0; j < 4; j++) {
            int col = col0 + tx * 4 + j;
            float val = acc[i][j];
            if (ACCUM) val += C[(size_t)row * M + col];
            if (BIASRELU) { val += bias[col]; val = fmaxf(val, 0.f); }
            C[(size_t)row * M + col] = val;
        }
    }
}

// ---------------- GCN aggregation (warp per node, float2 lanes) ----------------
__global__ void gcn_agg_kernel(const float* __restrict__ h0, const float* __restrict__ b_gcn,
                               const int* __restrict__ rs, const int* __restrict__ csrc,
                               const int* __restrict__ cnt, float* __restrict__ hout) {
    int node = (blockIdx.x * blockDim.x + threadIdx.x) >> 5;
    int lane = threadIdx.x & 31;
    if (node >= NN) return;
    int beg = rs[node], end = rs[node + 1];
    float dinv_d = rsqrtf((float)(end - beg + 1));
    const float2* H = (const float2*)h0;
    float ax = 0.f, ay = 0.f;
    for (int p = beg; p < end; p++) {
        int s = csrc[p];
        float ds = rsqrtf((float)(cnt[s] + 1));
        float2 hv = H[(size_t)s * 32 + lane];
        ax += hv.x * ds; ay += hv.y * ds;
    }
    float2 hd = H[(size_t)node * 32 + lane];
    ax = (ax + hd.x * dinv_d) * dinv_d;
    ay = (ay + hd.y * dinv_d) * dinv_d;
    float2 b = ((const float2*)b_gcn)[lane];
    float2 o;
    o.x = fmaxf(ax + b.x, 0.f);
    o.y = fmaxf(ay + b.y, 0.f);
    ((float2*)hout)[(size_t)node * 32 + lane] = o;
}

// ---------------- attention logits: a_s[n,h], a_d[n,h] ----------------
__global__ void att_kernel(const float* __restrict__ g,
                           const float* __restrict__ att_src,
                           const float* __restrict__ att_dst,
                           float* __restrict__ as_, float* __restrict__ ad_) {
    int node = (blockIdx.x * blockDim.x + threadIdx.x) >> 5;
    int lane = threadIdx.x & 31;
    if (node >= NN) return;
    const float4* G  = (const float4*)g;
    const float4* AS = (const float4*)att_src;
    const float4* AD = (const float4*)att_dst;
    float4 ga = G[(size_t)node * 64 + lane];         // j = 4*lane       (heads 0/1)
    float4 gb = G[(size_t)node * 64 + 32 + lane];    // j = 128 + 4*lane (heads 2/3)
    float4 wsa = AS[lane],      wsb = AS[32 + lane];
    float4 wda = AD[lane],      wdb = AD[32 + lane];
    float psa = ga.x * wsa.x + ga.y * wsa.y + ga.z * wsa.z + ga.w * wsa.w;
    float psb = gb.x * wsb.x + gb.y * wsb.y + gb.z * wsb.z + gb.w * wsb.w;
    float pda = ga.x * wda.x + ga.y * wda.y + ga.z * wda.z + ga.w * wda.w;
    float pdb = gb.x * wdb.x + gb.y * wdb.y + gb.z * wdb.z + gb.w * wdb.w;
    #pragma unroll
    for (int off = 8; off; off >>= 1) {
        psa += __shfl_down_sync(0xffffffffu, psa, off, 16);
        psb += __shfl_down_sync(0xffffffffu, psb, off, 16);
        pda += __shfl_down_sync(0xffffffffu, pda, off, 16);
        pdb += __shfl_down_sync(0xffffffffu, pdb, off, 16);
    }
    if ((lane & 15) == 0) {
        int h = lane >> 4;  // 0 or 1
        as_[node * 4 + h]     = psa;
        as_[node * 4 + 2 + h] = psb;
        ad_[node * 4 + h]     = pda;
        ad_[node * 4 + 2 + h] = pdb;
    }
}

// ---------------- GAT aggregation (warp per node, fused softmax) ----------------
__global__ void gat_agg_kernel(const float* __restrict__ g,
                               const float* __restrict__ as_,
                               const float* __restrict__ ad_,
                               const float* __restrict__ b_gat,
                               const int* __restrict__ rs,
                               const int* __restrict__ csrc,
                               float* __restrict__ g2) {
    int node = (blockIdx.x * blockDim.x + threadIdx.x) >> 5;
    int lane = threadIdx.x & 31;
    if (node >= NN) return;
    int beg = rs[node], end = rs[node + 1];
    float4 adv = *(const float4*)(ad_ + 4 * node);
    float4 asd = *(const float4*)(as_ + 4 * node);
    // self-loop logits
    float e0s = lrelu(asd.x + adv.x), e1s = lrelu(asd.y + adv.y);
    float e2s = lrelu(asd.z + adv.z), e3s = lrelu(asd.w + adv.w);
    float m0 = e0s, m1 = e1s, m2 = e2s, m3 = e3s;
    // pass 1: per-head max over in-edges (lanes parallel over edges)
    for (int p = beg + lane; p < end; p += 32) {
        int s = csrc[p];
        float4 av = *(const float4*)(as_ + 4 * s);
        m0 = fmaxf(m0, lrelu(av.x + adv.x));
        m1 = fmaxf(m1, lrelu(av.y + adv.y));
        m2 = fmaxf(m2, lrelu(av.z + adv.z));
        m3 = fmaxf(m3, lrelu(av.w + adv.w));
    }
    #pragma unroll
    for (int off = 16; off; off >>= 1) {
        m0 = fmaxf(m0, __shfl_xor_sync(0xffffffffu, m0, off));
        m1 = fmaxf(m1, __shfl_xor_sync(0xffffffffu, m1, off));
        m2 = fmaxf(m2, __shfl_xor_sync(0xffffffffu, m2, off));
        m3 = fmaxf(m3, __shfl_xor_sync(0xffffffffu, m3, off));
    }
    // per-lane head-component selectors (lanes 0..3 produce the 4 exps per edge)
    int c = lane & 3;
    float adc = c == 0 ? adv.x : c == 1 ? adv.y : c == 2 ? adv.z : adv.w;
    float mc  = c == 0 ? m0    : c == 1 ? m1    : c == 2 ? m2    : m3;
    int hsel = lane >> 4;
    float acc0 = 0.f, acc1 = 0.f, acc2 = 0.f, acc3 = 0.f;
    float acc4 = 0.f, acc5 = 0.f, acc6 = 0.f, acc7 = 0.f;
    float z0 = 0.f, z1 = 0.f, z2 = 0.f, z3 = 0.f;
    const float4* G = (const float4*)g;
    // pass 2: weighted accumulate (warp gathers full 256-float row per edge)
    for (int p = beg; p < end; p++) {
        int s = csrc[p];
        float4 av = *(const float4*)(as_ + 4 * s);
        float ac = c == 0 ? av.x : c == 1 ? av.y : c == 2 ? av.z : av.w;
        float wl = expf(lrelu(ac + adc) - mc);  // one warp-wide MUFU op, 4 useful lanes
        float w0 = __shfl_sync(0xffffffffu, wl, 0);
        float w1 = __shfl_sync(0xffffffffu, wl, 1);
        float w2 = __shfl_sync(0xffffffffu, wl, 2);
        float w3 = __shfl_sync(0xffffffffu, wl, 3);
        z0 += w0; z1 += w1; z2 += w2; z3 += w3;
        float wa = hsel ? w1 : w0;
        float wb = hsel ? w3 : w2;
        float4 ga = G[(size_t)s * 64 + lane];
        float4 gb = G[(size_t)s * 64 + 32 + lane];
        acc0 += ga.x * wa; acc1 += ga.y * wa; acc2 += ga.z * wa; acc3 += ga.w * wa;
        acc4 += gb.x * wb; acc5 += gb.y * wb; acc6 += gb.z * wb; acc7 += gb.w * wb;
    }
    // self loop
    float w0s = expf(e0s - m0), w1s = expf(e1s - m1);
    float w2s = expf(e2s - m2), w3s = expf(e3s - m3);
    z0 += w0s; z1 += w1s; z2 += w2s; z3 += w3s;
    {
        float wa = hsel ? w1s : w0s;
        float wb = hsel ? w3s : w2s;
        float4 ga = G[(size_t)node * 64 + lane];
        float4 gb = G[(size_t)node * 64 + 32 + lane];
        acc0 += ga.x * wa; acc1 += ga.y * wa; acc2 += ga.z * wa; acc3 += ga.w * wa;
        acc4 += gb.x * wb; acc5 += gb.y * wb; acc6 += gb.z * wb; acc7 += gb.w * wb;
    }
    float ia = 1.f / ((hsel ? z1 : z0) + 1e-16f);
    float ib = 1.f / ((hsel ? z3 : z2) + 1e-16f);
    const float4* BG = (const float4*)b_gat;
    float4 ba = BG[lane], bb = BG[32 + lane];
    float4 oa, ob;
    oa.x = fmaxf(acc0 * ia + ba.x, 0.f);
    oa.y = fmaxf(acc1 * ia + ba.y, 0.f);
    oa.z = fmaxf(acc2 * ia + ba.z, 0.f);
    oa.w = fmaxf(acc3 * ia + ba.w, 0.f);
    ob.x = fmaxf(acc4 * ib + bb.x, 0.f);
    ob.y = fmaxf(acc5 * ib + bb.y, 0.f);
    ob.z = fmaxf(acc6 * ib + bb.z, 0.f);
    ob.w = fmaxf(acc7 * ib + bb.w, 0.f);
    ((float4*)g2)[(size_t)node * 64 + lane]      = oa;
    ((float4*)g2)[(size_t)node * 64 + 32 + lane] = ob;
}

// ---------------- SAGE mean aggregation ----------------
__global__ void sage_agg_kernel(const float* __restrict__ g2,
                                const int* __restrict__ rs, const int* __restrict__ csrc,
                                float* __restrict__ mean) {
    int node = (blockIdx.x * blockDim.x + threadIdx.x) >> 5;
    int lane = threadIdx.x & 31;
    if (node >= NN) return;
    int beg = rs[node], end = rs[node + 1];
    const float4* G = (const float4*)g2;
    float4 a = make_float4(0.f, 0.f, 0.f, 0.f);
    float4 b = make_float4(0.f, 0.f, 0.f, 0.f);
    for (int p = beg; p < end; p++) {
        int s = csrc[p];
        float4 ga = G[(size_t)s * 64 + lane];
        float4 gb = G[(size_t)s * 64 + 32 + lane];
        a.x += ga.x; a.y += ga.y; a.z += ga.z; a.w += ga.w;
        b.x += gb.x; b.y += gb.y; b.z += gb.z; b.w += gb.w;
    }
    float inv = 1.f / fmaxf((float)(end - beg), 1.f);
    a.x *= inv; a.y *= inv; a.z *= inv; a.w *= inv;
    b.x *= inv; b.y *= inv; b.z *= inv; b.w *= inv;
    ((float4*)mean)[(size_t)node * 64 + lane]      = a;
    ((float4*)mean)[(size_t)node * 64 + 32 + lane] = b;
}

// ---------------- edge MLP + sigmoid (warp per edge) ----------------
__global__ void edge_kernel(const int* __restrict__ src, const int* __restrict__ dst,
                            const float* __restrict__ u, const float* __restrict__ v,
                            const float* __restrict__ b1, const float* __restrict__ W2,
                            const float* __restrict__ b2, float* __restrict__ out) {
    int e = (blockIdx.x * blockDim.x + threadIdx.x) >> 5;
    int lane = threadIdx.x & 31;
    if (e >= EE) return;
    int si = src[e], di = dst[e];
    float2 uu = ((const float2*)u)[(size_t)si * 32 + lane];
    float2 vv = ((const float2*)v)[(size_t)di * 32 + lane];
    float2 bb = ((const float2*)b1)[lane];
    float2 ww = ((const float2*)W2)[lane];
    float t0 = fmaxf(uu.x + vv.x + bb.x, 0.f);
    float t1 = fmaxf(uu.y + vv.y + bb.y, 0.f);
    float p = t0 * ww.x + t1 * ww.y;
    #pragma unroll
    for (int off = 16; off; off >>= 1) p += __shfl_xor_sync(0xffffffffu, p, off);
    if (lane == 0) out[e] = 1.f / (1.f + expf(-(p + b2[0])));
}

// ---------------- launch ----------------
extern "C" void kernel_launch(void* const* d_in, const int* in_sizes, int n_in,
                              void* d_out, int out_size) {
    const float* x        = (const float*)d_in[0];
    const int*   ei       = (const int*)  d_in[1];
    const float* W_gcn    = (const float*)d_in[2];
    const float* b_gcn    = (const float*)d_in[3];
    const float* W_gat    = (const float*)d_in[4];
    const float* att_src  = (const float*)d_in[5];
    const float* att_dst  = (const float*)d_in[6];
    const float* b_gat    = (const float*)d_in[7];
    const float* W_sage_l = (const float*)d_in[8];
    const float* b_sage   = (const float*)d_in[9];
    const float* W_sage_r = (const float*)d_in[10];
    const float* W1       = (const float*)d_in[11];
    const float* b1       = (const float*)d_in[12];
    const float* W2       = (const float*)d_in[13];
    const float* b2       = (const float*)d_in[14];
    float* out = (float*)d_out;
    const int* src = ei;
    const int* dst = ei + EE;

    float *h0, *h, *g, *g2, *mn, *s, *u, *v, *as_, *ad_;
    int *cnt, *cur, *rs, *csrc;
    cudaGetSymbolAddress((void**)&h0,  g_h0);
    cudaGetSymbolAddress((void**)&h,   g_h);
    cudaGetSymbolAddress((void**)&g,   g_g);
    cudaGetSymbolAddress((void**)&g2,  g_g2);
    cudaGetSymbolAddress((void**)&mn,  g_mn);
    cudaGetSymbolAddress((void**)&s,   g_s);
    cudaGetSymbolAddress((void**)&u,   g_u);
    cudaGetSymbolAddress((void**)&v,   g_v);
    cudaGetSymbolAddress((void**)&as_, g_as);
    cudaGetSymbolAddress((void**)&ad_, g_ad);
    cudaGetSymbolAddress((void**)&cnt, g_cnt);
    cudaGetSymbolAddress((void**)&cur, g_cur);
    cudaGetSymbolAddress((void**)&rs,  g_rs);
    cudaGetSymbolAddress((void**)&csrc, g_csrc);

    const int NB_NODE = (NN + 255) / 256;          // thread-per-node kernels
    const int NB_EDGE = (EE + 255) / 256;          // thread-per-edge kernels
    const int NB_NW   = (NN * 32 + 255) / 256;     // warp-per-node kernels (6250)
    const int NB_EW   = (EE * 32 + 255) / 256;     // warp-per-edge kernels (100000)
    const int NT64    = (NN + 63) / 64;            // GEMM row tiles (782)

    // CSR build (by dst)
    init_kernel<<<NB_NODE, 256>>>(cnt, cur);
    hist_kernel<<<NB_EDGE, 256>>>(dst, cnt);
    scan_kernel<<<1, 1024>>>(cnt, rs);
    fill_kernel<<<NB_EDGE, 256>>>(src, dst, rs, cur, csrc);

    // GCN: h0 = x @ W_gcn ; h = relu(norm-agg(h0) + b_gcn)
    gemm64<false, false><<<dim3(1, NT64), 256>>>(x, W_gcn, h0, nullptr, NN, 128, 64);
    gcn_agg_kernel<<<NB_NW, 256>>>(h0, b_gcn, rs, csrc, cnt, h);

    // GAT: g = h @ W_gat ; logits ; softmax-agg ; g2 = relu(agg + b_gat)
    gemm64<false, false><<<dim3(4, NT64), 256>>>(h, W_gat, g, nullptr, NN, 64, 256);
    att_kernel<<<NB_NW, 256>>>(g, att_src, att_dst, as_, ad_);
    gat_agg_kernel<<<NB_NW, 256>>>(g, as_, ad_, b_gat, rs, csrc, g2);

    // SAGE: mean-agg ; s = relu(mean@Wl + g2@Wr + b_sage)
    sage_agg_kernel<<<NB_NW, 256>>>(g2, rs, csrc, mn);
    gemm64<false, false><<<dim3(1, NT64), 256>>>(mn, W_sage_l, s, nullptr, NN, 256, 64);
    gemm64<true,  true ><<<dim3(1, NT64), 256>>>(g2, W_sage_r, s, b_sage, NN, 256, 64);

    // edge MLP split: u = s@W1[:64], v = s@W1[64:]
    gemm64<false, false><<<dim3(1, NT64), 256>>>(s, W1,           u, nullptr, NN, 64, 64);
    gemm64<false, false><<<dim3(1, NT64), 256>>>(s, W1 + 64 * 64, v, nullptr, NN, 64, 64);

    // per-edge: sigmoid(relu(u[src]+v[dst]+b1) . W2 + b2)
    edge_kernel<<<NB_EW, 256>>>(src, dst, u, v, b1, W2, b2, out);
}

// round 2
// speedup vs baseline: 1.3010x; 1.3010x over previous
#include <cuda_runtime.h>
#include <math.h>

#define NN   50000
#define EE   800000
#define H_   64
#define GD   256   // HEADS*H
#define NBLK 196   // ceil(NN/256)

// ---------------- scratch (static device arrays; no allocation) ----------------
__device__ float g_h0[NN * H_];    // x @ W_gcn
__device__ float g_h [NN * H_];    // GCN output (relu)
__device__ float g_g [NN * GD];    // h @ W_gat
__device__ float g_g2[NN * GD];    // GAT output (relu)
__device__ float g_mn[NN * GD];    // SAGE mean aggregate
__device__ float g_s [NN * H_];    // SAGE output
__device__ float g_uv[NN * 128];   // [u | v] per node
__device__ float g_w1p[64 * 128];  // packed W1
__device__ float g_as[NN * 4];     // attention src logits
__device__ float g_ad[NN * 4];     // attention dst logits
__device__ float g_dinv[NN];       // rsqrt(deg+1)
__device__ int   g_cnt[NN];        // in-degree (no self loop)
__device__ int   g_cur[NN];        // fill cursor
__device__ int   g_rs [NN + 1];    // CSR row starts (by dst)
__device__ int   g_bsum[NBLK];     // block sums for scan
__device__ int   g_csrc[EE];       // CSR: src node per slot

__device__ __forceinline__ float lrelu(float x) { return x > 0.f ? x : 0.2f * x; }

// ---------------- CSR build ----------------
__global__ void init_kernel(int* __restrict__ cnt, int* __restrict__ cur) {
    int i = blockIdx.x * blockDim.x + threadIdx.x;
    if (i < NN) { cnt[i] = 0; cur[i] = 0; }
}

__global__ void hist_kernel(const int* __restrict__ dst, int* __restrict__ cnt) {
    int e = blockIdx.x * blockDim.x + threadIdx.x;
    if (e * 4 < EE) {
        int4 d = ((const int4*)dst)[e];
        atomicAdd(&cnt[d.x], 1); atomicAdd(&cnt[d.y], 1);
        atomicAdd(&cnt[d.z], 1); atomicAdd(&cnt[d.w], 1);
    }
}

// two-level scan: block partial sums -> scan partials -> per-block scan + apply
__global__ void blocksum_kernel(const int* __restrict__ cnt, int* __restrict__ bsum) {
    __shared__ int ws[8];
    int i = blockIdx.x * 256 + threadIdx.x;
    int v = (i < NN) ? cnt[i] : 0;
    #pragma unroll
    for (int off = 16; off; off >>= 1) v += __shfl_down_sync(0xffffffffu, v, off);
    if ((threadIdx.x & 31) == 0) ws[threadIdx.x >> 5] = v;
    __syncthreads();
    if (threadIdx.x < 8) {
        int t = ws[threadIdx.x];
        #pragma unroll
        for (int off = 4; off; off >>= 1) t += __shfl_down_sync(0xffu, t, off);
        if (threadIdx.x == 0) bsum[blockIdx.x] = t;
    }
}

__global__ void scanb_kernel(int* __restrict__ bsum) {
    __shared__ int buf[256];
    int tid = threadIdx.x;
    int v = (tid < NBLK) ? bsum[tid] : 0;
    buf[tid] = v;
    __syncthreads();
    #pragma unroll
    for (int off = 1; off < 256; off <<= 1) {
        int t = (tid >= off) ? buf[tid - off] : 0;
        __syncthreads();
        buf[tid] += t;
        __syncthreads();
    }
    if (tid < NBLK) bsum[tid] = buf[tid] - v;  // exclusive
}

__global__ void rs_kernel(const int* __restrict__ cnt, const int* __restrict__ bsum,
                          int* __restrict__ rs, float* __restrict__ dinv) {
    __shared__ int buf[256];
    int tid = threadIdx.x;
    int i = blockIdx.x * 256 + tid;
    int v = (i < NN) ? cnt[i] : 0;
    buf[tid] = v;
    __syncthreads();
    #pragma unroll
    for (int off = 1; off < 256; off <<= 1) {
        int t = (tid >= off) ? buf[tid - off] : 0;
        __syncthreads();
        buf[tid] += t;
        __syncthreads();
    }
    if (i < NN) {
        rs[i] = bsum[blockIdx.x] + buf[tid] - v;
        dinv[i] = rsqrtf((float)(v + 1));
    }
    if (i == 0) rs[NN] = EE;
}

__global__ void fill_kernel(const int* __restrict__ src, const int* __restrict__ dst,
                            const int* __restrict__ rs, int* __restrict__ cur,
                            int* __restrict__ csrc) {
    int e = blockIdx.x * blockDim.x + threadIdx.x;
    if (e < EE) {
        int d = dst[e];
        int pos = atomicAdd(&cur[d], 1);
        csrc[rs[d] + pos] = src[e];
    }
}

// ---------------- tiled GEMM: C[n,M] = A[n,K] @ W[K,M] ----------------
// 64x64 tile, 4x4 micro, register-prefetch pipelined, float4 smem reads.
template <bool ACCUM, bool BIASRELU>
__global__ void gemm64(const float* __restrict__ A, const float* __restrict__ W,
                       float* __restrict__ C, const float* __restrict__ bias,
                       int n, int K, int M) {
    __shared__ float As[32][64];
    __shared__ float Ws[32][68];
    int row0 = blockIdx.y * 64;
    int col0 = blockIdx.x * 64;
    int tid = threadIdx.x;
    int tx = tid & 15, ty = tid >> 4;

    // A-load map: 2 float4 per thread (64 rows x 8 float4-k)
    int ra0 = tid >> 3,          ka0 = tid & 7;
    int ra1 = (tid + 256) >> 3,  ka1 = (tid + 256) & 7;
    // W-load map: 2 float4 per thread (32 k x 16 float4-cols)
    int kw0 = tid >> 4,          cw0 = tid & 15;
    int kw1 = (tid + 256) >> 4,  cw1 = (tid + 256) & 15;

    float4 pa0, pa1, pw0, pw1;
    {
        int r;
        r = row0 + ra0;
        pa0 = (r < n) ? *(const float4*)(A + (size_t)r * K + ka0 * 4)
                      : make_float4(0.f, 0.f, 0.f, 0.f);
        r = row0 + ra1;
        pa1 = (r < n) ? *(const float4*)(A + (size_t)r * K + ka1 * 4)
                      : make_float4(0.f, 0.f, 0.f, 0.f);
        pw0 = *(const float4*)(W + (size_t)kw0 * M + col0 + cw0 * 4);
        pw1 = *(const float4*)(W + (size_t)kw1 * M + col0 + cw1 * 4);
    }

    float acc[4][4] = {};
    for (int k0 = 0; k0 < K; k0 += 32) {
        // deposit prefetched tile
        As[ka0 * 4 + 0][ra0] = pa0.x; As[ka0 * 4 + 1][ra0] = pa0.y;
        As[ka0 * 4 + 2][ra0] = pa0.z; As[ka0 * 4 + 3][ra0] = pa0.w;
        As[ka1 * 4 + 0][ra1] = pa1.x; As[ka1 * 4 + 1][ra1] = pa1.y;
        As[ka1 * 4 + 2][ra1] = pa1.z; As[ka1 * 4 + 3][ra1] = pa1.w;
        *(float4*)&Ws[kw0][cw0 * 4] = pw0;
        *(float4*)&Ws[kw1][cw1 * 4] = pw1;
        __syncthreads();

        // prefetch next tile while computing
        int kn = k0 + 32;
        if (kn < K) {
            int r;
            r = row0 + ra0;
            pa0 = (r < n) ? *(const float4*)(A + (size_t)r * K + kn + ka0 * 4)
                          : make_float4(0.f, 0.f, 0.f, 0.f);
            r = row0 + ra1;
            pa1 = (r < n) ? *(const float4*)(A + (size_t)r * K + kn + ka1 * 4)
                          : make_float4(0.f, 0.f, 0.f, 0.f);
            pw0 = *(const float4*)(W + (size_t)(kn + kw0) * M + col0 + cw0 * 4);
            pw1 = *(const float4*)(W + (size_t)(kn + kw1) * M + col0 + cw1 * 4);
        }

        #pragma unroll
        for (int kk = 0; kk < 32; kk++) {
            float4 a = *(const float4*)&As[kk][ty * 4];
            float4 b = *(const float4*)&Ws[kk][tx * 4];
            acc[0][0] += a.x * b.x; acc[0][1] += a.x * b.y;
            acc[0][2] += a.x * b.z; acc[0][3] += a.x * b.w;
            acc[1][0] += a.y * b.x; acc[1][1] += a.y * b.y;
            acc[1][2] += a.y * b.z; acc[1][3] += a.y * b.w;
            acc[2][0] += a.z * b.x; acc[2][1] += a.z * b.y;
            acc[2][2] += a.z * b.z; acc[2][3] += a.z * b.w;
            acc[3][0] += a.w * b.x; acc[3][1] += a.w * b.y;
            acc[3][2] += a.w * b.z; acc[3][3] += a.w * b.w;
        }
        __syncthreads();
    }

    float4 bv;
    if (BIASRELU) bv = *(const float4*)(bias + col0 + tx * 4);
    #pragma unroll
    for (int i = 0; i < 4; i++) {
        int row = row0 + ty * 4 + i;
        if (row >= n) continue;
        float* cp = C + (size_t)row * M + col0 + tx * 4;
        float4 val = make_float4(acc[i][0], acc[i][1], acc[i][2], acc[i][3]);
        if (ACCUM) {
            float4 old = *(float4*)cp;
            val.x += old.x; val.y += old.y; val.z += old.z; val.w += old.w;
        }
        if (BIASRELU) {
            val.x = fmaxf(val.x + bv.x, 0.f); val.y = fmaxf(val.y + bv.y, 0.f);
            val.z = fmaxf(val.z + bv.z, 0.f); val.w = fmaxf(val.w + bv.w, 0.f);
        }
        *(float4*)cp = val;
    }
}

// ---------------- pack W1 [128,64] -> W1p [64,128] = [W1top | W1bot] ----------------
__global__ void pack_w1_kernel(const float* __restrict__ W1, float* __restrict__ W1p) {
    int i = blockIdx.x * 256 + threadIdx.x;
    if (i >= 64 * 128) return;
    int k = i >> 7, m = i & 127;
    W1p[i] = (m < 64) ? W1[k * 64 + m] : W1[(64 + k) * 64 + (m - 64)];
}

// ---------------- GCN aggregation (warp per node, float2 lanes) ----------------
__global__ void gcn_agg_kernel(const float* __restrict__ h0, const float* __restrict__ b_gcn,
                               const int* __restrict__ rs, const int* __restrict__ csrc,
                               const float* __restrict__ dinv, float* __restrict__ hout) {
    int node = (blockIdx.x * blockDim.x + threadIdx.x) >> 5;
    int lane = threadIdx.x & 31;
    if (node >= NN) return;
    int beg = rs[node], end = rs[node + 1];
    float dinv_d = dinv[node];
    const float2* H = (const float2*)h0;
    float ax = 0.f, ay = 0.f;
    for (int p = beg; p < end; p++) {
        int s = csrc[p];
        float ds = dinv[s];
        float2 hv = H[(size_t)s * 32 + lane];
        ax += hv.x * ds; ay += hv.y * ds;
    }
    float2 hd = H[(size_t)node * 32 + lane];
    ax = (ax + hd.x * dinv_d) * dinv_d;
    ay = (ay + hd.y * dinv_d) * dinv_d;
    float2 b = ((const float2*)b_gcn)[lane];
    float2 o;
    o.x = fmaxf(ax + b.x, 0.f);
    o.y = fmaxf(ay + b.y, 0.f);
    ((float2*)hout)[(size_t)node * 32 + lane] = o;
}

// ---------------- attention logits: a_s[n,h], a_d[n,h] ----------------
__global__ void att_kernel(const float* __restrict__ g,
                           const float* __restrict__ att_src,
                           const float* __restrict__ att_dst,
                           float* __restrict__ as_, float* __restrict__ ad_) {
    int node = (blockIdx.x * blockDim.x + threadIdx.x) >> 5;
    int lane = threadIdx.x & 31;
    if (node >= NN) return;
    const float4* G  = (const float4*)g;
    const float4* AS = (const float4*)att_src;
    const float4* AD = (const float4*)att_dst;
    float4 ga = G[(size_t)node * 64 + lane];
    float4 gb = G[(size_t)node * 64 + 32 + lane];
    float4 wsa = AS[lane],      wsb = AS[32 + lane];
    float4 wda = AD[lane],      wdb = AD[32 + lane];
    float psa = ga.x * wsa.x + ga.y * wsa.y + ga.z * wsa.z + ga.w * wsa.w;
    float psb = gb.x * wsb.x + gb.y * wsb.y + gb.z * wsb.z + gb.w * wsb.w;
    float pda = ga.x * wda.x + ga.y * wda.y + ga.z * wda.z + ga.w * wda.w;
    float pdb = gb.x * wdb.x + gb.y * wdb.y + gb.z * wdb.z + gb.w * wdb.w;
    #pragma unroll
    for (int off = 8; off; off >>= 1) {
        psa += __shfl_down_sync(0xffffffffu, psa, off, 16);
        psb += __shfl_down_sync(0xffffffffu, psb, off, 16);
        pda += __shfl_down_sync(0xffffffffu, pda, off, 16);
        pdb += __shfl_down_sync(0xffffffffu, pdb, off, 16);
    }
    if ((lane & 15) == 0) {
        int h = lane >> 4;
        as_[node * 4 + h]     = psa;
        as_[node * 4 + 2 + h] = psb;
        ad_[node * 4 + h]     = pda;
        ad_[node * 4 + 2 + h] = pdb;
    }
}

// ---------------- GAT aggregation (warp per node, fused softmax) ----------------
__global__ void gat_agg_kernel(const float* __restrict__ g,
                               const float* __restrict__ as_,
                               const float* __restrict__ ad_,
                               const float* __restrict__ b_gat,
                               const int* __restrict__ rs,
                               const int* __restrict__ csrc,
                               float* __restrict__ g2) {
    int node = (blockIdx.x * blockDim.x + threadIdx.x) >> 5;
    int lane = threadIdx.x & 31;
    if (node >= NN) return;
    int beg = rs[node], end = rs[node + 1];
    float4 adv = *(const float4*)(ad_ + 4 * node);
    float4 asd = *(const float4*)(as_ + 4 * node);
    float e0s = lrelu(asd.x + adv.x), e1s = lrelu(asd.y + adv.y);
    float e2s = lrelu(asd.z + adv.z), e3s = lrelu(asd.w + adv.w);
    float m0 = e0s, m1 = e1s, m2 = e2s, m3 = e3s;
    for (int p = beg + lane; p < end; p += 32) {
        int s = csrc[p];
        float4 av = *(const float4*)(as_ + 4 * s);
        m0 = fmaxf(m0, lrelu(av.x + adv.x));
        m1 = fmaxf(m1, lrelu(av.y + adv.y));
        m2 = fmaxf(m2, lrelu(av.z + adv.z));
        m3 = fmaxf(m3, lrelu(av.w + adv.w));
    }
    #pragma unroll
    for (int off = 16; off; off >>= 1) {
        m0 = fmaxf(m0, __shfl_xor_sync(0xffffffffu, m0, off));
        m1 = fmaxf(m1, __shfl_xor_sync(0xffffffffu, m1, off));
        m2 = fmaxf(m2, __shfl_xor_sync(0xffffffffu, m2, off));
        m3 = fmaxf(m3, __shfl_xor_sync(0xffffffffu, m3, off));
    }
    int c = lane & 3;
    float adc = c == 0 ? adv.x : c == 1 ? adv.y : c == 2 ? adv.z : adv.w;
    float mc  = c == 0 ? m0    : c == 1 ? m1    : c == 2 ? m2    : m3;
    int hsel = lane >> 4;
    float acc0 = 0.f, acc1 = 0.f, acc2 = 0.f, acc3 = 0.f;
    float acc4 = 0.f, acc5 = 0.f, acc6 = 0.f, acc7 = 0.f;
    float z0 = 0.f, z1 = 0.f, z2 = 0.f, z3 = 0.f;
    const float4* G = (const float4*)g;
    for (int p = beg; p < end; p++) {
        int s = csrc[p];
        float4 av = *(const float4*)(as_ + 4 * s);
        float ac = c == 0 ? av.x : c == 1 ? av.y : c == 2 ? av.z : av.w;
        float wl = expf(lrelu(ac + adc) - mc);
        float w0 = __shfl_sync(0xffffffffu, wl, 0);
        float w1 = __shfl_sync(0xffffffffu, wl, 1);
        float w2 = __shfl_sync(0xffffffffu, wl, 2);
        float w3 = __shfl_sync(0xffffffffu, wl, 3);
        z0 += w0; z1 += w1; z2 += w2; z3 += w3;
        float wa = hsel ? w1 : w0;
        float wb = hsel ? w3 : w2;
        float4 ga = G[(size_t)s * 64 + lane];
        float4 gb = G[(size_t)s * 64 + 32 + lane];
        acc0 += ga.x * wa; acc1 += ga.y * wa; acc2 += ga.z * wa; acc3 += ga.w * wa;
        acc4 += gb.x * wb; acc5 += gb.y * wb; acc6 += gb.z * wb; acc7 += gb.w * wb;
    }
    float w0s = expf(e0s - m0), w1s = expf(e1s - m1);
    float w2s = expf(e2s - m2), w3s = expf(e3s - m3);
    z0 += w0s; z1 += w1s; z2 += w2s; z3 += w3s;
    {
        float wa = hsel ? w1s : w0s;
        float wb = hsel ? w3s : w2s;
        float4 ga = G[(size_t)node * 64 + lane];
        float4 gb = G[(size_t)node * 64 + 32 + lane];
        acc0 += ga.x * wa; acc1 += ga.y * wa; acc2 += ga.z * wa; acc3 += ga.w * wa;
        acc4 += gb.x * wb; acc5 += gb.y * wb; acc6 += gb.z * wb; acc7 += gb.w * wb;
    }
    float ia = 1.f / ((hsel ? z1 : z0) + 1e-16f);
    float ib = 1.f / ((hsel ? z3 : z2) + 1e-16f);
    const float4* BG = (const float4*)b_gat;
    float4 ba = BG[lane], bb = BG[32 + lane];
    float4 oa, ob;
    oa.x = fmaxf(acc0 * ia + ba.x, 0.f);
    oa.y = fmaxf(acc1 * ia + ba.y, 0.f);
    oa.z = fmaxf(acc2 * ia + ba.z, 0.f);
    oa.w = fmaxf(acc3 * ia + ba.w, 0.f);
    ob.x = fmaxf(acc4 * ib + bb.x, 0.f);
    ob.y = fmaxf(acc5 * ib + bb.y, 0.f);
    ob.z = fmaxf(acc6 * ib + bb.z, 0.f);
    ob.w = fmaxf(acc7 * ib + bb.w, 0.f);
    ((float4*)g2)[(size_t)node * 64 + lane]      = oa;
    ((float4*)g2)[(size_t)node * 64 + 32 + lane] = ob;
}

// ---------------- SAGE mean aggregation ----------------
__global__ void sage_agg_kernel(const float* __restrict__ g2,
                                const int* __restrict__ rs, const int* __restrict__ csrc,
                                float* __restrict__ mean) {
    int node = (blockIdx.x * blockDim.x + threadIdx.x) >> 5;
    int lane = threadIdx.x & 31;
    if (node >= NN) return;
    int beg = rs[node], end = rs[node + 1];
    const float4* G = (const float4*)g2;
    float4 a = make_float4(0.f, 0.f, 0.f, 0.f);
    float4 b = make_float4(0.f, 0.f, 0.f, 0.f);
    for (int p = beg; p < end; p++) {
        int s = csrc[p];
        float4 ga = G[(size_t)s * 64 + lane];
        float4 gb = G[(size_t)s * 64 + 32 + lane];
        a.x += ga.x; a.y += ga.y; a.z += ga.z; a.w += ga.w;
        b.x += gb.x; b.y += gb.y; b.z += gb.z; b.w += gb.w;
    }
    float inv = 1.f / fmaxf((float)(end - beg), 1.f);
    a.x *= inv; a.y *= inv; a.z *= inv; a.w *= inv;
    b.x *= inv; b.y *= inv; b.z *= inv; b.w *= inv;
    ((float4*)mean)[(size_t)node * 64 + lane]      = a;
    ((float4*)mean)[(size_t)node * 64 + 32 + lane] = b;
}

// ---------------- edge MLP + sigmoid (16 lanes per edge, 2 edges/warp) ----------------
__global__ void edge_kernel(const int* __restrict__ src, const int* __restrict__ dst,
                            const float* __restrict__ uv, const float* __restrict__ b1,
                            const float* __restrict__ W2, const float* __restrict__ b2,
                            float* __restrict__ out) {
    int idx = blockIdx.x * blockDim.x + threadIdx.x;
    int e = idx >> 4;
    int l = idx & 15;
    if (e >= EE) return;
    int si = src[e], di = dst[e];
    const float4* UV = (const float4*)uv;
    float4 uu = UV[(size_t)si * 32 + l];
    float4 vv = UV[(size_t)di * 32 + 16 + l];
    float4 bb = ((const float4*)b1)[l];
    float4 ww = ((const float4*)W2)[l];
    float p = fmaxf(uu.x + vv.x + bb.x, 0.f) * ww.x
            + fmaxf(uu.y + vv.y + bb.y, 0.f) * ww.y
            + fmaxf(uu.z + vv.z + bb.z, 0.f) * ww.z
            + fmaxf(uu.w + vv.w + bb.w, 0.f) * ww.w;
    #pragma unroll
    for (int off = 8; off; off >>= 1) p += __shfl_xor_sync(0xffffffffu, p, off);
    if (l == 0) out[e] = 1.f / (1.f + expf(-(p + b2[0])));
}

// ---------------- launch ----------------
extern "C" void kernel_launch(void* const* d_in, const int* in_sizes, int n_in,
                              void* d_out, int out_size) {
    const float* x        = (const float*)d_in[0];
    const int*   ei       = (const int*)  d_in[1];
    const float* W_gcn    = (const float*)d_in[2];
    const float* b_gcn    = (const float*)d_in[3];
    const float* W_gat    = (const float*)d_in[4];
    const float* att_src  = (const float*)d_in[5];
    const float* att_dst  = (const float*)d_in[6];
    const float* b_gat    = (const float*)d_in[7];
    const float* W_sage_l = (const float*)d_in[8];
    const float* b_sage   = (const float*)d_in[9];
    const float* W_sage_r = (const float*)d_in[10];
    const float* W1       = (const float*)d_in[11];
    const float* b1       = (const float*)d_in[12];
    const float* W2       = (const float*)d_in[13];
    const float* b2       = (const float*)d_in[14];
    float* out = (float*)d_out;
    const int* src = ei;
    const int* dst = ei + EE;

    float *h0, *h, *g, *g2, *mn, *s, *uv, *w1p, *as_, *ad_, *dinv;
    int *cnt, *cur, *rs, *bsum, *csrc;
    cudaGetSymbolAddress((void**)&h0,  g_h0);
    cudaGetSymbolAddress((void**)&h,   g_h);
    cudaGetSymbolAddress((void**)&g,   g_g);
    cudaGetSymbolAddress((void**)&g2,  g_g2);
    cudaGetSymbolAddress((void**)&mn,  g_mn);
    cudaGetSymbolAddress((void**)&s,   g_s);
    cudaGetSymbolAddress((void**)&uv,  g_uv);
    cudaGetSymbolAddress((void**)&w1p, g_w1p);
    cudaGetSymbolAddress((void**)&as_, g_as);
    cudaGetSymbolAddress((void**)&ad_, g_ad);
    cudaGetSymbolAddress((void**)&dinv, g_dinv);
    cudaGetSymbolAddress((void**)&cnt, g_cnt);
    cudaGetSymbolAddress((void**)&cur, g_cur);
    cudaGetSymbolAddress((void**)&rs,  g_rs);
    cudaGetSymbolAddress((void**)&bsum, g_bsum);
    cudaGetSymbolAddress((void**)&csrc, g_csrc);

    const int NB_NODE = (NN + 255) / 256;          // 196
    const int NB_EDGE = (EE + 255) / 256;          // 3125
    const int NB_E4   = (EE / 4 + 255) / 256;      // 782 (hist, 4 edges/thread)
    const int NB_NW   = (NN * 32 + 255) / 256;     // 6250 (warp per node)
    const int NB_E16  = (EE * 16 + 255) / 256;     // 50000 (16 lanes per edge)
    const int NT64    = (NN + 63) / 64;            // 782

    // CSR build (by dst)
    init_kernel<<<NB_NODE, 256>>>(cnt, cur);
    hist_kernel<<<NB_E4, 256>>>(dst, cnt);
    blocksum_kernel<<<NBLK, 256>>>(cnt, bsum);
    scanb_kernel<<<1, 256>>>(bsum);
    rs_kernel<<<NBLK, 256>>>(cnt, bsum, rs, dinv);
    fill_kernel<<<NB_EDGE, 256>>>(src, dst, rs, cur, csrc);
    pack_w1_kernel<<<32, 256>>>(W1, w1p);  // independent of graph state

    // GCN
    gemm64<false, false><<<dim3(1, NT64), 256>>>(x, W_gcn, h0, nullptr, NN, 128, 64);
    gcn_agg_kernel<<<NB_NW, 256>>>(h0, b_gcn, rs, csrc, dinv, h);

    // GAT
    gemm64<false, false><<<dim3(4, NT64), 256>>>(h, W_gat, g, nullptr, NN, 64, 256);
    att_kernel<<<NB_NW, 256>>>(g, att_src, att_dst, as_, ad_);
    gat_agg_kernel<<<NB_NW, 256>>>(g, as_, ad_, b_gat, rs, csrc, g2);

    // SAGE
    sage_agg_kernel<<<NB_NW, 256>>>(g2, rs, csrc, mn);
    gemm64<false, false><<<dim3(1, NT64), 256>>>(mn, W_sage_l, s, nullptr, NN, 256, 64);
    gemm64<true,  true ><<<dim3(1, NT64), 256>>>(g2, W_sage_r, s, b_sage, NN, 256, 64);

    // edge MLP: uv = s @ W1p  ([u|v] in one GEMM)
    gemm64<false, false><<<dim3(2, NT64), 256>>>(s, w1p, uv, nullptr, NN, 64, 128);

    // per-edge: sigmoid(relu(u[src]+v[dst]+b1) . W2 + b2)
    edge_kernel<<<NB_E16, 256>>>(src, dst, uv, b1, W2, b2, out);
}

// round 3
// speedup vs baseline: 1.4424x; 1.1086x over previous
#include <cuda_runtime.h>
#include <math.h>

#define NN   50000
#define EE   800000
#define H_   64
#define GD   256   // HEADS*H
#define NBLK 196   // ceil(NN/256)

// ---------------- scratch (static device arrays; no allocation) ----------------
__device__ float g_h0[NN * H_];    // x @ W_gcn
__device__ float g_h [NN * H_];    // GCN output (relu)
__device__ float g_g [NN * GD];    // h @ W_gat
__device__ float g_g2[NN * GD];    // GAT output (relu)
__device__ float g_y [NN * H_];    // g2 @ W_sage_l
__device__ float g_r [NN * H_];    // g2 @ W_sage_r
__device__ float g_s [NN * H_];    // SAGE output
__device__ float g_uv[NN * 128];   // [u | v] per node
__device__ float g_w1p[64 * 128];  // packed W1
__device__ float g_as[NN * 4];     // attention src logits
__device__ float g_ad[NN * 4];     // attention dst logits
__device__ float g_dinv[NN];       // rsqrt(deg+1)
__device__ int   g_cnt[NN];        // in-degree (no self loop)
__device__ int   g_cur[NN];        // fill cursor
__device__ int   g_rs [NN + 1];    // CSR row starts (by dst)
__device__ int   g_bsum[NBLK];     // block sums for scan
__device__ int   g_csrc[EE];       // CSR: src node per slot

__device__ __forceinline__ float lrelu(float x) { return x > 0.f ? x : 0.2f * x; }

// ---------------- CSR build ----------------
__global__ void init_kernel(int* __restrict__ cnt, int* __restrict__ cur) {
    int i = blockIdx.x * blockDim.x + threadIdx.x;
    if (i < NN) { cnt[i] = 0; cur[i] = 0; }
}

__global__ void hist_kernel(const int* __restrict__ dst, int* __restrict__ cnt) {
    int e = blockIdx.x * blockDim.x + threadIdx.x;
    if (e * 4 < EE) {
        int4 d = ((const int4*)dst)[e];
        atomicAdd(&cnt[d.x], 1); atomicAdd(&cnt[d.y], 1);
        atomicAdd(&cnt[d.z], 1); atomicAdd(&cnt[d.w], 1);
    }
}

__global__ void blocksum_kernel(const int* __restrict__ cnt, int* __restrict__ bsum) {
    __shared__ int ws[8];
    int i = blockIdx.x * 256 + threadIdx.x;
    int v = (i < NN) ? cnt[i] : 0;
    #pragma unroll
    for (int off = 16; off; off >>= 1) v += __shfl_down_sync(0xffffffffu, v, off);
    if ((threadIdx.x & 31) == 0) ws[threadIdx.x >> 5] = v;
    __syncthreads();
    if (threadIdx.x < 8) {
        int t = ws[threadIdx.x];
        #pragma unroll
        for (int off = 4; off; off >>= 1) t += __shfl_down_sync(0xffu, t, off);
        if (threadIdx.x == 0) bsum[blockIdx.x] = t;
    }
}

__global__ void scanb_kernel(int* __restrict__ bsum) {
    __shared__ int buf[256];
    int tid = threadIdx.x;
    int v = (tid < NBLK) ? bsum[tid] : 0;
    buf[tid] = v;
    __syncthreads();
    #pragma unroll
    for (int off = 1; off < 256; off <<= 1) {
        int t = (tid >= off) ? buf[tid - off] : 0;
        __syncthreads();
        buf[tid] += t;
        __syncthreads();
    }
    if (tid < NBLK) bsum[tid] = buf[tid] - v;  // exclusive
}

__global__ void rs_kernel(const int* __restrict__ cnt, const int* __restrict__ bsum,
                          int* __restrict__ rs, float* __restrict__ dinv) {
    __shared__ int buf[256];
    int tid = threadIdx.x;
    int i = blockIdx.x * 256 + tid;
    int v = (i < NN) ? cnt[i] : 0;
    buf[tid] = v;
    __syncthreads();
    #pragma unroll
    for (int off = 1; off < 256; off <<= 1) {
        int t = (tid >= off) ? buf[tid - off] : 0;
        __syncthreads();
        buf[tid] += t;
        __syncthreads();
    }
    if (i < NN) {
        rs[i] = bsum[blockIdx.x] + buf[tid] - v;
        dinv[i] = rsqrtf((float)(v + 1));
    }
    if (i == 0) rs[NN] = EE;
}

__global__ void fill_kernel(const int* __restrict__ src, const int* __restrict__ dst,
                            const int* __restrict__ rs, int* __restrict__ cur,
                            int* __restrict__ csrc) {
    int e = blockIdx.x * blockDim.x + threadIdx.x;
    if (e < EE) {
        int d = dst[e];
        int pos = atomicAdd(&cur[d], 1);
        csrc[rs[d] + pos] = src[e];
    }
}

// ---------------- tf32 tensor-core GEMM: C[n,M] = A[n,K] @ W[K,M] ----------------
// grid (M/64, ceil(n/64)), 128 threads (4 warps). Warp w: rows [row0+16w, +16).
// mma.m16n8k8.tf32, fragments loaded straight from gmem (A, W L1/L2 hot).
__device__ __forceinline__ unsigned f2tf(float x) {
    unsigned r;
    asm("cvt.rna.tf32.f32 %0, %1;" : "=r"(r) : "f"(x));
    return r;
}

__global__ void mma_gemm(const float* __restrict__ A, const float* __restrict__ W,
                         float* __restrict__ C, int n, int K, int M) {
    int warp = threadIdx.x >> 5;
    int lane = threadIdx.x & 31;
    int g = lane >> 2, t = lane & 3;
    int row0 = blockIdx.y * 64 + warp * 16;
    int col0 = blockIdx.x * 64;
    int r0 = row0 + g, r1 = row0 + g + 8;
    bool v0 = r0 < n, v1 = r1 < n;
    const float* a0p = A + (size_t)(v0 ? r0 : 0) * K + t;
    const float* a1p = A + (size_t)(v1 ? r1 : 0) * K + t;

    float acc[8][4];
    #pragma unroll
    for (int i = 0; i < 8; i++)
        #pragma unroll
        for (int j = 0; j < 4; j++) acc[i][j] = 0.f;

    for (int k0 = 0; k0 < K; k0 += 8) {
        unsigned a0 = v0 ? f2tf(a0p[k0])     : 0u;
        unsigned a2 = v0 ? f2tf(a0p[k0 + 4]) : 0u;
        unsigned a1 = v1 ? f2tf(a1p[k0])     : 0u;
        unsigned a3 = v1 ? f2tf(a1p[k0 + 4]) : 0u;
        const float* wp0 = W + (size_t)(k0 + t) * M + col0 + g;
        const float* wp1 = wp0 + 4 * (size_t)M;
        #pragma unroll
        for (int nt = 0; nt < 8; nt++) {
            unsigned b0 = f2tf(wp0[nt * 8]);
            unsigned b1 = f2tf(wp1[nt * 8]);
            asm("mma.sync.aligned.m16n8k8.row.col.f32.tf32.tf32.f32 "
                "{%0,%1,%2,%3}, {%4,%5,%6,%7}, {%8,%9}, {%0,%1,%2,%3};"
                : "+f"(acc[nt][0]), "+f"(acc[nt][1]), "+f"(acc[nt][2]), "+f"(acc[nt][3])
                : "r"(a0), "r"(a1), "r"(a2), "r"(a3), "r"(b0), "r"(b1));
        }
    }
    #pragma unroll
    for (int nt = 0; nt < 8; nt++) {
        int c = col0 + nt * 8 + 2 * t;
        if (v0) {
            C[(size_t)r0 * M + c]     = acc[nt][0];
            C[(size_t)r0 * M + c + 1] = acc[nt][1];
        }
        if (v1) {
            C[(size_t)r1 * M + c]     = acc[nt][2];
            C[(size_t)r1 * M + c + 1] = acc[nt][3];
        }
    }
}

// ---------------- pack W1 [128,64] -> W1p [64,128] = [W1top | W1bot] ----------------
__global__ void pack_w1_kernel(const float* __restrict__ W1, float* __restrict__ W1p) {
    int i = blockIdx.x * 256 + threadIdx.x;
    if (i >= 64 * 128) return;
    int k = i >> 7, m = i & 127;
    W1p[i] = (m < 64) ? W1[k * 64 + m] : W1[(64 + k) * 64 + (m - 64)];
}

// ---------------- GCN aggregation (warp per node, float2 lanes) ----------------
__global__ void gcn_agg_kernel(const float* __restrict__ h0, const float* __restrict__ b_gcn,
                               const int* __restrict__ rs, const int* __restrict__ csrc,
                               const float* __restrict__ dinv, float* __restrict__ hout) {
    int node = (blockIdx.x * blockDim.x + threadIdx.x) >> 5;
    int lane = threadIdx.x & 31;
    if (node >= NN) return;
    int beg = rs[node], end = rs[node + 1];
    float dinv_d = dinv[node];
    const float2* H = (const float2*)h0;
    float ax = 0.f, ay = 0.f;
    for (int p = beg; p < end; p++) {
        int s = csrc[p];
        float ds = dinv[s];
        float2 hv = H[(size_t)s * 32 + lane];
        ax += hv.x * ds; ay += hv.y * ds;
    }
    float2 hd = H[(size_t)node * 32 + lane];
    ax = (ax + hd.x * dinv_d) * dinv_d;
    ay = (ay + hd.y * dinv_d) * dinv_d;
    float2 b = ((const float2*)b_gcn)[lane];
    float2 o;
    o.x = fmaxf(ax + b.x, 0.f);
    o.y = fmaxf(ay + b.y, 0.f);
    ((float2*)hout)[(size_t)node * 32 + lane] = o;
}

// ---------------- attention logits ----------------
__global__ void att_kernel(const float* __restrict__ g,
                           const float* __restrict__ att_src,
                           const float* __restrict__ att_dst,
                           float* __restrict__ as_, float* __restrict__ ad_) {
    int node = (blockIdx.x * blockDim.x + threadIdx.x) >> 5;
    int lane = threadIdx.x & 31;
    if (node >= NN) return;
    const float4* G  = (const float4*)g;
    const float4* AS = (const float4*)att_src;
    const float4* AD = (const float4*)att_dst;
    float4 ga = G[(size_t)node * 64 + lane];
    float4 gb = G[(size_t)node * 64 + 32 + lane];
    float4 wsa = AS[lane],      wsb = AS[32 + lane];
    float4 wda = AD[lane],      wdb = AD[32 + lane];
    float psa = ga.x * wsa.x + ga.y * wsa.y + ga.z * wsa.z + ga.w * wsa.w;
    float psb = gb.x * wsb.x + gb.y * wsb.y + gb.z * wsb.z + gb.w * wsb.w;
    float pda = ga.x * wda.x + ga.y * wda.y + ga.z * wda.z + ga.w * wda.w;
    float pdb = gb.x * wdb.x + gb.y * wdb.y + gb.z * wdb.z + gb.w * wdb.w;
    #pragma unroll
    for (int off = 8; off; off >>= 1) {
        psa += __shfl_down_sync(0xffffffffu, psa, off, 16);
        psb += __shfl_down_sync(0xffffffffu, psb, off, 16);
        pda += __shfl_down_sync(0xffffffffu, pda, off, 16);
        pdb += __shfl_down_sync(0xffffffffu, pdb, off, 16);
    }
    if ((lane & 15) == 0) {
        int h = lane >> 4;
        as_[node * 4 + h]     = psa;
        as_[node * 4 + 2 + h] = psb;
        ad_[node * 4 + h]     = pda;
        ad_[node * 4 + 2 + h] = pdb;
    }
}

// ---------------- GAT aggregation (warp per node, fused softmax) ----------------
__global__ void gat_agg_kernel(const float* __restrict__ g,
                               const float* __restrict__ as_,
                               const float* __restrict__ ad_,
                               const float* __restrict__ b_gat,
                               const int* __restrict__ rs,
                               const int* __restrict__ csrc,
                               float* __restrict__ g2) {
    int node = (blockIdx.x * blockDim.x + threadIdx.x) >> 5;
    int lane = threadIdx.x & 31;
    if (node >= NN) return;
    int beg = rs[node], end = rs[node + 1];
    float4 adv = *(const float4*)(ad_ + 4 * node);
    float4 asd = *(const float4*)(as_ + 4 * node);
    float e0s = lrelu(asd.x + adv.x), e1s = lrelu(asd.y + adv.y);
    float e2s = lrelu(asd.z + adv.z), e3s = lrelu(asd.w + adv.w);
    float m0 = e0s, m1 = e1s, m2 = e2s, m3 = e3s;
    for (int p = beg + lane; p < end; p += 32) {
        int s = csrc[p];
        float4 av = *(const float4*)(as_ + 4 * s);
        m0 = fmaxf(m0, lrelu(av.x + adv.x));
        m1 = fmaxf(m1, lrelu(av.y + adv.y));
        m2 = fmaxf(m2, lrelu(av.z + adv.z));
        m3 = fmaxf(m3, lrelu(av.w + adv.w));
    }
    #pragma unroll
    for (int off = 16; off; off >>= 1) {
        m0 = fmaxf(m0, __shfl_xor_sync(0xffffffffu, m0, off));
        m1 = fmaxf(m1, __shfl_xor_sync(0xffffffffu, m1, off));
        m2 = fmaxf(m2, __shfl_xor_sync(0xffffffffu, m2, off));
        m3 = fmaxf(m3, __shfl_xor_sync(0xffffffffu, m3, off));
    }
    int c = lane & 3;
    float adc = c == 0 ? adv.x : c == 1 ? adv.y : c == 2 ? adv.z : adv.w;
    float mc  = c == 0 ? m0    : c == 1 ? m1    : c == 2 ? m2    : m3;
    int hsel = lane >> 4;
    float acc0 = 0.f, acc1 = 0.f, acc2 = 0.f, acc3 = 0.f;
    float acc4 = 0.f, acc5 = 0.f, acc6 = 0.f, acc7 = 0.f;
    float z0 = 0.f, z1 = 0.f, z2 = 0.f, z3 = 0.f;
    const float4* G = (const float4*)g;
    for (int p = beg; p < end; p++) {
        int s = csrc[p];
        float4 av = *(const float4*)(as_ + 4 * s);
        float ac = c == 0 ? av.x : c == 1 ? av.y : c == 2 ? av.z : av.w;
        float wl = expf(lrelu(ac + adc) - mc);
        float w0 = __shfl_sync(0xffffffffu, wl, 0);
        float w1 = __shfl_sync(0xffffffffu, wl, 1);
        float w2 = __shfl_sync(0xffffffffu, wl, 2);
        float w3 = __shfl_sync(0xffffffffu, wl, 3);
        z0 += w0; z1 += w1; z2 += w2; z3 += w3;
        float wa = hsel ? w1 : w0;
        float wb = hsel ? w3 : w2;
        float4 ga = G[(size_t)s * 64 + lane];
        float4 gb = G[(size_t)s * 64 + 32 + lane];
        acc0 += ga.x * wa; acc1 += ga.y * wa; acc2 += ga.z * wa; acc3 += ga.w * wa;
        acc4 += gb.x * wb; acc5 += gb.y * wb; acc6 += gb.z * wb; acc7 += gb.w * wb;
    }
    float w0s = expf(e0s - m0), w1s = expf(e1s - m1);
    float w2s = expf(e2s - m2), w3s = expf(e3s - m3);
    z0 += w0s; z1 += w1s; z2 += w2s; z3 += w3s;
    {
        float wa = hsel ? w1s : w0s;
        float wb = hsel ? w3s : w2s;
        float4 ga = G[(size_t)node * 64 + lane];
        float4 gb = G[(size_t)node * 64 + 32 + lane];
        acc0 += ga.x * wa; acc1 += ga.y * wa; acc2 += ga.z * wa; acc3 += ga.w * wa;
        acc4 += gb.x * wb; acc5 += gb.y * wb; acc6 += gb.z * wb; acc7 += gb.w * wb;
    }
    float ia = 1.f / ((hsel ? z1 : z0) + 1e-16f);
    float ib = 1.f / ((hsel ? z3 : z2) + 1e-16f);
    const float4* BG = (const float4*)b_gat;
    float4 ba = BG[lane], bb = BG[32 + lane];
    float4 oa, ob;
    oa.x = fmaxf(acc0 * ia + ba.x, 0.f);
    oa.y = fmaxf(acc1 * ia + ba.y, 0.f);
    oa.z = fmaxf(acc2 * ia + ba.z, 0.f);
    oa.w = fmaxf(acc3 * ia + ba.w, 0.f);
    ob.x = fmaxf(acc4 * ib + bb.x, 0.f);
    ob.y = fmaxf(acc5 * ib + bb.y, 0.f);
    ob.z = fmaxf(acc6 * ib + bb.z, 0.f);
    ob.w = fmaxf(acc7 * ib + bb.w, 0.f);
    ((float4*)g2)[(size_t)node * 64 + lane]      = oa;
    ((float4*)g2)[(size_t)node * 64 + 32 + lane] = ob;
}

// ---------------- SAGE fused: s = relu(sum(y[nbr])/cnt + r + b) ----------------
__global__ void sage_fuse_kernel(const float* __restrict__ y, const float* __restrict__ r,
                                 const float* __restrict__ b_sage,
                                 const int* __restrict__ rs, const int* __restrict__ csrc,
                                 float* __restrict__ s) {
    int node = (blockIdx.x * blockDim.x + threadIdx.x) >> 5;
    int lane = threadIdx.x & 31;
    if (node >= NN) return;
    int beg = rs[node], end = rs[node + 1];
    const float2* Y = (const float2*)y;
    float ax = 0.f, ay = 0.f;
    for (int p = beg; p < end; p++) {
        int sn = csrc[p];
        float2 yv = Y[(size_t)sn * 32 + lane];
        ax += yv.x; ay += yv.y;
    }
    float inv = 1.f / fmaxf((float)(end - beg), 1.f);
    float2 rv = ((const float2*)r)[(size_t)node * 32 + lane];
    float2 bv = ((const float2*)b_sage)[lane];
    float2 o;
    o.x = fmaxf(ax * inv + rv.x + bv.x, 0.f);
    o.y = fmaxf(ay * inv + rv.y + bv.y, 0.f);
    ((float2*)s)[(size_t)node * 32 + lane] = o;
}

// ---------------- edge MLP + sigmoid (16 lanes per edge) ----------------
__global__ void edge_kernel(const int* __restrict__ src, const int* __restrict__ dst,
                            const float* __restrict__ uv, const float* __restrict__ b1,
                            const float* __restrict__ W2, const float* __restrict__ b2,
                            float* __restrict__ out) {
    int idx = blockIdx.x * blockDim.x + threadIdx.x;
    int e = idx >> 4;
    int l = idx & 15;
    if (e >= EE) return;
    int si = src[e], di = dst[e];
    const float4* UV = (const float4*)uv;
    float4 uu = UV[(size_t)si * 32 + l];
    float4 vv = UV[(size_t)di * 32 + 16 + l];
    float4 bb = ((const float4*)b1)[l];
    float4 ww = ((const float4*)W2)[l];
    float p = fmaxf(uu.x + vv.x + bb.x, 0.f) * ww.x
            + fmaxf(uu.y + vv.y + bb.y, 0.f) * ww.y
            + fmaxf(uu.z + vv.z + bb.z, 0.f) * ww.z
            + fmaxf(uu.w + vv.w + bb.w, 0.f) * ww.w;
    #pragma unroll
    for (int off = 8; off; off >>= 1) p += __shfl_xor_sync(0xffffffffu, p, off);
    if (l == 0) out[e] = 1.f / (1.f + expf(-(p + b2[0])));
}

// ---------------- launch ----------------
extern "C" void kernel_launch(void* const* d_in, const int* in_sizes, int n_in,
                              void* d_out, int out_size) {
    const float* x        = (const float*)d_in[0];
    const int*   ei       = (const int*)  d_in[1];
    const float* W_gcn    = (const float*)d_in[2];
    const float* b_gcn    = (const float*)d_in[3];
    const float* W_gat    = (const float*)d_in[4];
    const float* att_src  = (const float*)d_in[5];
    const float* att_dst  = (const float*)d_in[6];
    const float* b_gat    = (const float*)d_in[7];
    const float* W_sage_l = (const float*)d_in[8];
    const float* b_sage   = (const float*)d_in[9];
    const float* W_sage_r = (const float*)d_in[10];
    const float* W1       = (const float*)d_in[11];
    const float* b1       = (const float*)d_in[12];
    const float* W2       = (const float*)d_in[13];
    const float* b2       = (const float*)d_in[14];
    float* out = (float*)d_out;
    const int* src = ei;
    const int* dst = ei + EE;

    float *h0, *h, *g, *g2, *y, *r, *s, *uv, *w1p, *as_, *ad_, *dinv;
    int *cnt, *cur, *rs, *bsum, *csrc;
    cudaGetSymbolAddress((void**)&h0,  g_h0);
    cudaGetSymbolAddress((void**)&h,   g_h);
    cudaGetSymbolAddress((void**)&g,   g_g);
    cudaGetSymbolAddress((void**)&g2,  g_g2);
    cudaGetSymbolAddress((void**)&y,   g_y);
    cudaGetSymbolAddress((void**)&r,   g_r);
    cudaGetSymbolAddress((void**)&s,   g_s);
    cudaGetSymbolAddress((void**)&uv,  g_uv);
    cudaGetSymbolAddress((void**)&w1p, g_w1p);
    cudaGetSymbolAddress((void**)&as_, g_as);
    cudaGetSymbolAddress((void**)&ad_, g_ad);
    cudaGetSymbolAddress((void**)&dinv, g_dinv);
    cudaGetSymbolAddress((void**)&cnt, g_cnt);
    cudaGetSymbolAddress((void**)&cur, g_cur);
    cudaGetSymbolAddress((void**)&rs,  g_rs);
    cudaGetSymbolAddress((void**)&bsum, g_bsum);
    cudaGetSymbolAddress((void**)&csrc, g_csrc);

    const int NB_NODE = (NN + 255) / 256;          // 196
    const int NB_EDGE = (EE + 255) / 256;          // 3125
    const int NB_E4   = (EE / 4 + 255) / 256;      // 782
    const int NB_NW   = (NN * 32 + 255) / 256;     // 6250
    const int NB_E16  = (EE * 16 + 255) / 256;     // 50000
    const int NT64    = (NN + 63) / 64;            // 782 (mma row tiles)

    // CSR build (by dst)
    init_kernel<<<NB_NODE, 256>>>(cnt, cur);
    hist_kernel<<<NB_E4, 256>>>(dst, cnt);
    blocksum_kernel<<<NBLK, 256>>>(cnt, bsum);
    scanb_kernel<<<1, 256>>>(bsum);
    rs_kernel<<<NBLK, 256>>>(cnt, bsum, rs, dinv);
    fill_kernel<<<NB_EDGE, 256>>>(src, dst, rs, cur, csrc);
    pack_w1_kernel<<<32, 256>>>(W1, w1p);

    // GCN
    mma_gemm<<<dim3(1, NT64), 128>>>(x, W_gcn, h0, NN, 128, 64);
    gcn_agg_kernel<<<NB_NW, 256>>>(h0, b_gcn, rs, csrc, dinv, h);

    // GAT
    mma_gemm<<<dim3(4, NT64), 128>>>(h, W_gat, g, NN, 64, 256);
    att_kernel<<<NB_NW, 256>>>(g, att_src, att_dst, as_, ad_);
    gat_agg_kernel<<<NB_NW, 256>>>(g, as_, ad_, b_gat, rs, csrc, g2);

    // SAGE: y = g2@Wl, r = g2@Wr, then fused gather (aggregate y, not g2)
    mma_gemm<<<dim3(1, NT64), 128>>>(g2, W_sage_l, y, NN, 256, 64);
    mma_gemm<<<dim3(1, NT64), 128>>>(g2, W_sage_r, r, NN, 256, 64);
    sage_fuse_kernel<<<NB_NW, 256>>>(y, r, b_sage, rs, csrc, s);

    // edge MLP: uv = s @ W1p
    mma_gemm<<<dim3(2, NT64), 128>>>(s, w1p, uv, NN, 64, 128);

    // per-edge: sigmoid(relu(u[src]+v[dst]+b1) . W2 + b2)
    edge_kernel<<<NB_E16, 256>>>(src, dst, uv, b1, W2, b2, out);
}